// round 1
// baseline (speedup 1.0000x reference)
#include <cuda_runtime.h>

// ParallelTransport: out[b,i,j,:,:] = 6-term Taylor exp of
//   M[b,i,j] = sum_d (x[b,j,d]-x[b,i,d]) * A[b,j,d,:,:]
//
// Grid: (b, j, i-tile) -> 4*512*4 = 8192 CTAs, 256 threads.
// Phase 1: register-blocked SGEMM  M_tile[128 x 64] = Y[128 x 512] @ A_j[512 x 64]
//          with Y[i,d] = x[b,j,d]-x[b,i,d] formed during the smem load.
// Phase 2: per-8x8-matrix Taylor (8 lanes/matrix, one row per lane, M in regs).

#define SS       512
#define DD       512
#define TILE_I   128
#define DK       32
#define THREADS  256
#define XSTRIDE  (DK + 4)    // 36 floats
#define ASTRIDE  (64 + 4)    // 68 floats

#define XS_BYTES (TILE_I * XSTRIDE * 4)              // 18432
#define AS_BYTES (DK * ASTRIDE * 4)                  // 8704
#define MS_BYTES (TILE_I * ASTRIDE * 4)              // 34816
#define SM_BYTES (MS_BYTES > (XS_BYTES + AS_BYTES) ? MS_BYTES : (XS_BYTES + AS_BYTES))

__global__ __launch_bounds__(THREADS, 2)
void pt_kernel(const float* __restrict__ x,
               const float* __restrict__ A,
               float* __restrict__ out)
{
    __shared__ __align__(16) char smraw[SM_BYTES];
    float (*Xs)[XSTRIDE] = reinterpret_cast<float (*)[XSTRIDE]>(smraw);
    float (*As)[ASTRIDE] = reinterpret_cast<float (*)[ASTRIDE]>(smraw + XS_BYTES);
    float (*Ms)[ASTRIDE] = reinterpret_cast<float (*)[ASTRIDE]>(smraw);

    const int blk = blockIdx.x;
    const int it  = blk & 3;
    const int j   = (blk >> 2) & (SS - 1);
    const int b   = blk >> 11;
    const int i0  = it * TILE_I;

    const int tid = threadIdx.x;
    const int klg = tid & 7;     // 0..7  -> kl columns klg*8 .. +7
    const int ig  = tid >> 3;    // 0..31 -> rows ig*4 .. +3

    const float* Xb = x + (size_t)b * SS * DD;
    const float* xi_base = Xb + (size_t)i0 * DD;
    const float* xj = Xb + (size_t)j * DD;
    const float* Ab = A + ((size_t)b * SS + j) * DD * 64;

    float acc[4][8];
#pragma unroll
    for (int ii = 0; ii < 4; ii++)
#pragma unroll
        for (int c = 0; c < 8; c++) acc[ii][c] = 0.0f;

    for (int dk = 0; dk < DD; dk += DK) {
        // ---- stage A chunk: A[b,j, dk..dk+DK, 0..63], contiguous 2048 floats
#pragma unroll
        for (int f = tid; f < DK * 16; f += THREADS) {      // 512 float4
            int d = f >> 4, q = f & 15;
            float4 v = *(const float4*)(Ab + (size_t)(dk + d) * 64 + q * 4);
            *(float4*)&As[d][q * 4] = v;
        }
        // ---- stage X chunk with x_j - x_i applied: 128 rows x DK
#pragma unroll
        for (int f = tid; f < TILE_I * (DK / 4); f += THREADS) {  // 1024 float4
            int row = f >> 3, q = f & 7;
            float4 vi = *(const float4*)(xi_base + (size_t)row * DD + dk + q * 4);
            float4 vj = *(const float4*)(xj + dk + q * 4);
            float4 vv = make_float4(vj.x - vi.x, vj.y - vi.y, vj.z - vi.z, vj.w - vi.w);
            *(float4*)&Xs[row][q * 4] = vv;
        }
        __syncthreads();

#pragma unroll 8
        for (int d = 0; d < DK; d++) {
            float xv[4];
#pragma unroll
            for (int ii = 0; ii < 4; ii++) xv[ii] = Xs[ig * 4 + ii][d];
            float4 a0 = *(const float4*)&As[d][klg * 8];
            float4 a1 = *(const float4*)&As[d][klg * 8 + 4];
            float av[8] = {a0.x, a0.y, a0.z, a0.w, a1.x, a1.y, a1.z, a1.w};
#pragma unroll
            for (int ii = 0; ii < 4; ii++)
#pragma unroll
                for (int c = 0; c < 8; c++)
                    acc[ii][c] = fmaf(xv[ii], av[c], acc[ii][c]);
        }
        __syncthreads();
    }

    // ---- dump M tile into shared (aliases Xs/As; last __syncthreads covers WAR)
#pragma unroll
    for (int ii = 0; ii < 4; ii++) {
        *(float4*)&Ms[ig * 4 + ii][klg * 8] =
            make_float4(acc[ii][0], acc[ii][1], acc[ii][2], acc[ii][3]);
        *(float4*)&Ms[ig * 4 + ii][klg * 8 + 4] =
            make_float4(acc[ii][4], acc[ii][5], acc[ii][6], acc[ii][7]);
    }
    __syncthreads();

    // ---- Taylor: 8 lanes per 8x8 matrix, one row per lane, 4 passes
    const int r     = tid & 7;
    const int mbase = tid >> 3;   // 0..31

#pragma unroll 1
    for (int p = 0; p < 4; p++) {
        const int m = p * 32 + mbase;

        // full M in registers (compile-time indexed only)
        float Mreg[8][8];
#pragma unroll
        for (int k = 0; k < 8; k++) {
            float4 u0 = *(const float4*)&Ms[m][k * 8];
            float4 u1 = *(const float4*)&Ms[m][k * 8 + 4];
            Mreg[k][0] = u0.x; Mreg[k][1] = u0.y; Mreg[k][2] = u0.z; Mreg[k][3] = u0.w;
            Mreg[k][4] = u1.x; Mreg[k][5] = u1.y; Mreg[k][6] = u1.z; Mreg[k][7] = u1.w;
        }
        // own row loaded from smem (runtime r can't index Mreg without spilling)
        float Mp[8], res[8];
        {
            float4 u0 = *(const float4*)&Ms[m][r * 8];
            float4 u1 = *(const float4*)&Ms[m][r * 8 + 4];
            Mp[0] = u0.x; Mp[1] = u0.y; Mp[2] = u0.z; Mp[3] = u0.w;
            Mp[4] = u1.x; Mp[5] = u1.y; Mp[6] = u1.z; Mp[7] = u1.w;
        }
#pragma unroll
        for (int c = 0; c < 8; c++) res[c] = Mp[c];

        const float invn[7] = {0.f, 1.f, 0.5f, 1.f / 3.f, 0.25f, 0.2f, 1.f / 6.f};
#pragma unroll
        for (int n = 2; n <= 6; n++) {
            float nw[8];
#pragma unroll
            for (int c = 0; c < 8; c++) nw[c] = 0.0f;
#pragma unroll
            for (int k = 0; k < 8; k++) {
                float s = Mp[k];
#pragma unroll
                for (int c = 0; c < 8; c++)
                    nw[c] = fmaf(s, Mreg[k][c], nw[c]);
            }
            float sc = invn[n];
#pragma unroll
            for (int c = 0; c < 8; c++) {
                nw[c] *= sc;
                Mp[c] = nw[c];
                res[c] += nw[c];
            }
        }
        res[r] += 1.0f;   // identity

        size_t off = (((size_t)b * SS + (i0 + m)) * SS + j) * 64 + (size_t)r * 8;
        *(float4*)(out + off)     = make_float4(res[0], res[1], res[2], res[3]);
        *(float4*)(out + off + 4) = make_float4(res[4], res[5], res[6], res[7]);
    }
}

extern "C" void kernel_launch(void* const* d_in, const int* in_sizes, int n_in,
                              void* d_out, int out_size)
{
    const float* x = (const float*)d_in[0];   // [4,512,512]
    const float* A = (const float*)d_in[1];   // [4,512,512,8,8]
    float* out = (float*)d_out;               // [4,512,512,8,8]
    (void)in_sizes; (void)n_in; (void)out_size;

    dim3 grid(4 * 512 * 4);   // (b, j, i-tile), i-tile fastest
    dim3 block(THREADS);
    pt_kernel<<<grid, block>>>(x, A, out);
}